// round 1
// baseline (speedup 1.0000x reference)
#include <cuda_runtime.h>

#define N_NODES 100000
#define N_EDGES 1600000
#define D 128
#define NGRAPH 64
#define DOUT 16
#define LN_EPS 1e-5f

// ---------------- scratch (static device globals; no allocation) ----------------
__device__ float g_A[N_NODES * D];        // GEMM output / gather source
__device__ float g_B[N_NODES * D];        // aggregation target / LN output
__device__ float g_deg[N_NODES];
__device__ float g_dinv[N_NODES];
__device__ float g_pooled[NGRAPH * D];
__device__ float g_cnt[NGRAPH];

// ---------------- init ----------------
__global__ void k_init() {
    int i = blockIdx.x * blockDim.x + threadIdx.x;
    if (i < N_NODES) g_deg[i] = 1.0f;            // self-loop
    if (i < NGRAPH * D) g_pooled[i] = 0.0f;
    if (i < NGRAPH) g_cnt[i] = 0.0f;
}

__global__ void k_zeroB() {
    int i = blockIdx.x * blockDim.x + threadIdx.x;
    int stride = gridDim.x * blockDim.x;
    float4 z = make_float4(0.f, 0.f, 0.f, 0.f);
    float4* p = reinterpret_cast<float4*>(g_B);
    for (int j = i; j < N_NODES * D / 4; j += stride) p[j] = z;
}

__global__ void k_degree(const int* __restrict__ dst) {
    int i = blockIdx.x * blockDim.x + threadIdx.x;
    if (i < N_EDGES) atomicAdd(&g_deg[dst[i]], 1.0f);
}

__global__ void k_dinv() {
    int i = blockIdx.x * blockDim.x + threadIdx.x;
    if (i < N_NODES) g_dinv[i] = rsqrtf(g_deg[i]);
}

// ---------------- GEMM: C[M,128] = A[M,128] @ W[128,128] ----------------
// 64x128 output tile per 256-thread block; BK=64; 32 outputs/thread (4 rows x 8 cols).
__global__ void __launch_bounds__(256) k_gemm(const float* __restrict__ A,
                                              const float* __restrict__ W,
                                              float* __restrict__ C) {
    __shared__ float As[64][64];     // [row][k]
    __shared__ float Bs[64][128];    // [k][col]
    int tid = threadIdx.x;
    int tx = tid & 15;               // col group: cols tx*8 .. tx*8+7
    int ty = tid >> 4;               // row group: rows ty*4 .. ty*4+3
    int rowBase = blockIdx.x * 64;

    float acc[4][8];
#pragma unroll
    for (int i = 0; i < 4; i++)
#pragma unroll
        for (int j = 0; j < 8; j++) acc[i][j] = 0.f;

    for (int k0 = 0; k0 < 128; k0 += 64) {
        // load A tile: 64 rows x 64 k-cols = 1024 float4
#pragma unroll
        for (int i = 0; i < 4; i++) {
            int idx = tid + i * 256;
            int r = idx >> 4;
            int c4 = idx & 15;
            int grow = rowBase + r;
            float4 v = make_float4(0.f, 0.f, 0.f, 0.f);
            if (grow < N_NODES)
                v = *reinterpret_cast<const float4*>(&A[grow * D + k0 + c4 * 4]);
            *reinterpret_cast<float4*>(&As[r][c4 * 4]) = v;
        }
        // load W tile: 64 k-rows x 128 cols = 2048 float4
#pragma unroll
        for (int i = 0; i < 8; i++) {
            int idx = tid + i * 256;
            int r = idx >> 5;
            int c4 = idx & 31;
            *reinterpret_cast<float4*>(&Bs[r][c4 * 4]) =
                *reinterpret_cast<const float4*>(&W[(k0 + r) * D + c4 * 4]);
        }
        __syncthreads();

#pragma unroll
        for (int k = 0; k < 64; k++) {
            float a0 = As[ty * 4 + 0][k];
            float a1 = As[ty * 4 + 1][k];
            float a2 = As[ty * 4 + 2][k];
            float a3 = As[ty * 4 + 3][k];
            float4 b0 = *reinterpret_cast<float4*>(&Bs[k][tx * 8]);
            float4 b1 = *reinterpret_cast<float4*>(&Bs[k][tx * 8 + 4]);
            float bb[8] = {b0.x, b0.y, b0.z, b0.w, b1.x, b1.y, b1.z, b1.w};
            float aa[4] = {a0, a1, a2, a3};
#pragma unroll
            for (int i = 0; i < 4; i++)
#pragma unroll
                for (int j = 0; j < 8; j++) acc[i][j] = fmaf(aa[i], bb[j], acc[i][j]);
        }
        __syncthreads();
    }

#pragma unroll
    for (int i = 0; i < 4; i++) {
        int row = rowBase + ty * 4 + i;
        if (row < N_NODES) {
            float4 o0 = make_float4(acc[i][0], acc[i][1], acc[i][2], acc[i][3]);
            float4 o1 = make_float4(acc[i][4], acc[i][5], acc[i][6], acc[i][7]);
            *reinterpret_cast<float4*>(&C[row * D + tx * 8]) = o0;
            *reinterpret_cast<float4*>(&C[row * D + tx * 8 + 4]) = o1;
        }
    }
}

// ---------------- edge scatter: out[dst] += h[src] * dinv[src]*dinv[dst] ----------------
// One warp per edge, float4 per lane (128 features), vector red.global.add.
__global__ void __launch_bounds__(256) k_scatter(const float* __restrict__ h,
                                                 const int* __restrict__ src,
                                                 const int* __restrict__ dst,
                                                 float* __restrict__ out) {
    int e = blockIdx.x * 8 + (threadIdx.x >> 5);
    if (e >= N_EDGES) return;
    int lane = threadIdx.x & 31;
    int s = __ldg(&src[e]);
    int d = __ldg(&dst[e]);
    float nrm = __ldg(&g_dinv[s]) * __ldg(&g_dinv[d]);
    float4 v = *reinterpret_cast<const float4*>(&h[s * D + lane * 4]);
    float* p = &out[d * D + lane * 4];
    asm volatile("red.global.add.v4.f32 [%0], {%1, %2, %3, %4};"
                 :: "l"(p), "f"(v.x * nrm), "f"(v.y * nrm), "f"(v.z * nrm), "f"(v.w * nrm)
                 : "memory");
}

// ---------------- self-loop + bias + LayerNorm + ReLU (in place on agg) ----------------
// One warp per node; 4 features per lane.
__global__ void __launch_bounds__(256) k_blr(float* __restrict__ agg,
                                             const float* __restrict__ h,
                                             const float* __restrict__ bias,
                                             const float* __restrict__ lng,
                                             const float* __restrict__ lnb) {
    int node = blockIdx.x * 8 + (threadIdx.x >> 5);
    if (node >= N_NODES) return;
    int lane = threadIdx.x & 31;
    float di = g_dinv[node];
    float sc = di * di;
    int base = node * D + lane * 4;

    float4 v = *reinterpret_cast<float4*>(&agg[base]);
    float4 hv = *reinterpret_cast<const float4*>(&h[base]);
    float4 b4 = *reinterpret_cast<const float4*>(&bias[lane * 4]);
    v.x = fmaf(hv.x, sc, v.x) + b4.x;
    v.y = fmaf(hv.y, sc, v.y) + b4.y;
    v.z = fmaf(hv.z, sc, v.z) + b4.z;
    v.w = fmaf(hv.w, sc, v.w) + b4.w;

    float s = v.x + v.y + v.z + v.w;
#pragma unroll
    for (int o = 16; o > 0; o >>= 1) s += __shfl_xor_sync(0xFFFFFFFFu, s, o);
    float mu = s * (1.0f / D);

    float dx = v.x - mu, dy = v.y - mu, dz = v.z - mu, dw = v.w - mu;
    float sq = dx * dx + dy * dy + dz * dz + dw * dw;
#pragma unroll
    for (int o = 16; o > 0; o >>= 1) sq += __shfl_xor_sync(0xFFFFFFFFu, sq, o);
    float rs = rsqrtf(sq * (1.0f / D) + LN_EPS);

    float4 g4 = *reinterpret_cast<const float4*>(&lng[lane * 4]);
    float4 p4 = *reinterpret_cast<const float4*>(&lnb[lane * 4]);
    v.x = fmaxf(dx * rs * g4.x + p4.x, 0.f);
    v.y = fmaxf(dy * rs * g4.y + p4.y, 0.f);
    v.z = fmaxf(dz * rs * g4.z + p4.z, 0.f);
    v.w = fmaxf(dw * rs * g4.w + p4.w, 0.f);
    *reinterpret_cast<float4*>(&agg[base]) = v;
}

// ---------------- graph mean pool (batch is sorted) ----------------
#define POOL_CHUNK 128
__global__ void __launch_bounds__(128) k_pool(const float* __restrict__ h,
                                              const int* __restrict__ batch) {
    int f = threadIdx.x;
    int start = blockIdx.x * POOL_CHUNK;
    if (start >= N_NODES) return;
    int end = min(start + POOL_CHUNK, N_NODES);
    float sum = 0.f;
    int cur = __ldg(&batch[start]);
    for (int n = start; n < end; n++) {
        int gg = __ldg(&batch[n]);
        if (gg != cur) {
            atomicAdd(&g_pooled[cur * D + f], sum);
            sum = 0.f;
            cur = gg;
        }
        sum += h[n * D + f];
    }
    atomicAdd(&g_pooled[cur * D + f], sum);
}

__global__ void __launch_bounds__(256) k_cnt(const int* __restrict__ batch) {
    __shared__ float hist[NGRAPH];
    if (threadIdx.x < NGRAPH) hist[threadIdx.x] = 0.f;
    __syncthreads();
    for (int n = blockIdx.x * blockDim.x + threadIdx.x; n < N_NODES;
         n += gridDim.x * blockDim.x)
        atomicAdd(&hist[batch[n]], 1.0f);
    __syncthreads();
    if (threadIdx.x < NGRAPH) atomicAdd(&g_cnt[threadIdx.x], hist[threadIdx.x]);
}

// ---------------- head: out[g,o] = (pooled[g]/cnt[g]) @ lin_w + lin_b ----------------
__global__ void __launch_bounds__(1024) k_final(const float* __restrict__ lw,
                                                const float* __restrict__ lb,
                                                float* __restrict__ out) {
    int t = threadIdx.x;            // 1024 = 64 graphs x 16 outputs
    int g = t >> 4;
    int o = t & 15;
    float acc = 0.f;
#pragma unroll 8
    for (int f = 0; f < D; f++) acc += g_pooled[g * D + f] * __ldg(&lw[f * DOUT + o]);
    out[t] = acc / fmaxf(g_cnt[g], 1.0f) + __ldg(&lb[o]);
}

// ---------------- launch ----------------
extern "C" void kernel_launch(void* const* d_in, const int* in_sizes, int n_in,
                              void* d_out, int out_size) {
    const float* x     = (const float*)d_in[0];
    const int*   ei    = (const int*)d_in[1];
    const int*   src   = ei;
    const int*   dst   = ei + N_EDGES;
    const int*   batch = (const int*)d_in[2];
    const float* W1    = (const float*)d_in[3];
    const float* b1    = (const float*)d_in[4];
    const float* W2    = (const float*)d_in[5];
    const float* b2    = (const float*)d_in[6];
    const float* lng   = (const float*)d_in[7];
    const float* lnb   = (const float*)d_in[8];
    const float* lw    = (const float*)d_in[9];
    const float* lbias = (const float*)d_in[10];
    float* out = (float*)d_out;

    float *pA = nullptr, *pB = nullptr;
    cudaGetSymbolAddress((void**)&pA, g_A);
    cudaGetSymbolAddress((void**)&pB, g_B);

    const int T = 256;
    // init + degree + dinv
    k_init<<<(N_NODES + T - 1) / T, T>>>();
    k_degree<<<(N_EDGES + T - 1) / T, T>>>(dst);
    k_dinv<<<(N_NODES + T - 1) / T, T>>>();

    // layer 1: h = x@W1 -> A ; agg(A) -> B ; +b1, LN, ReLU in place on B
    k_gemm<<<(N_NODES + 63) / 64, 256>>>(x, W1, pA);
    k_zeroB<<<512, 256>>>();
    k_scatter<<<(N_EDGES + 7) / 8, 256>>>(pA, src, dst, pB);
    k_blr<<<(N_NODES + 7) / 8, 256>>>(pB, pA, b1, lng, lnb);

    // layer 2: h = B@W2 -> A ; zero B ; agg(A) -> B ; +b2, LN, ReLU
    k_gemm<<<(N_NODES + 63) / 64, 256>>>(pB, W2, pA);
    k_zeroB<<<512, 256>>>();
    k_scatter<<<(N_EDGES + 7) / 8, 256>>>(pA, src, dst, pB);
    k_blr<<<(N_NODES + 7) / 8, 256>>>(pB, pA, b2, lng, lnb);

    // pool + head
    k_pool<<<(N_NODES + POOL_CHUNK - 1) / POOL_CHUNK, 128>>>(pB, batch);
    k_cnt<<<64, 256>>>(batch);
    k_final<<<1, 1024>>>(lw, lbias, out);
}

// round 2
// speedup vs baseline: 1.8546x; 1.8546x over previous
#include <cuda_runtime.h>

#define N_NODES 100000
#define N_EDGES 1600000
#define D 128
#define NGRAPH 64
#define DOUT 16
#define LN_EPS 1e-5f
#define SCAN_B 1024
#define SCAN_NB ((N_NODES + SCAN_B - 1) / SCAN_B)   // 98

// ---------------- scratch (static device globals; no allocation) ----------------
__device__ float g_A[N_NODES * D];
__device__ float g_B[N_NODES * D];
__device__ int   g_cnti[N_NODES];
__device__ int   g_offs[N_NODES + 1];
__device__ int   g_cursor[N_NODES];
__device__ int   g_adj[N_EDGES];
__device__ int   g_bsum[SCAN_NB];
__device__ float g_dinv[N_NODES];
__device__ float g_pooled[NGRAPH * D];
__device__ float g_gcnt[NGRAPH];

// ---------------- init ----------------
__global__ void k_init() {
    int i = blockIdx.x * blockDim.x + threadIdx.x;
    if (i < N_NODES) g_cnti[i] = 0;
    if (i < NGRAPH * D) g_pooled[i] = 0.0f;
    if (i < NGRAPH) g_gcnt[i] = 0.0f;
}

__global__ void k_count(const int* __restrict__ dst) {
    int i = blockIdx.x * blockDim.x + threadIdx.x;
    if (i < N_EDGES) atomicAdd(&g_cnti[dst[i]], 1);
}

__global__ void k_dinv() {
    int i = blockIdx.x * blockDim.x + threadIdx.x;
    if (i < N_NODES) g_dinv[i] = rsqrtf((float)(g_cnti[i] + 1));  // +1 self-loop
}

// ---------------- prefix scan (3 tiny kernels) ----------------
__global__ void k_scan1() {
    __shared__ int sh[SCAN_B];
    int i = blockIdx.x * SCAN_B + threadIdx.x;
    int v = (i < N_NODES) ? g_cnti[i] : 0;
    sh[threadIdx.x] = v;
    __syncthreads();
#pragma unroll
    for (int o = 1; o < SCAN_B; o <<= 1) {
        int t = (threadIdx.x >= o) ? sh[threadIdx.x - o] : 0;
        __syncthreads();
        sh[threadIdx.x] += t;
        __syncthreads();
    }
    if (i < N_NODES) g_offs[i + 1] = sh[threadIdx.x];
    if (threadIdx.x == SCAN_B - 1) g_bsum[blockIdx.x] = sh[SCAN_B - 1];
}

__global__ void k_scan2() {
    if (threadIdx.x == 0) {
        int run = 0;
        for (int b = 0; b < SCAN_NB; b++) {
            int t = g_bsum[b];
            g_bsum[b] = run;
            run += t;
        }
    }
}

__global__ void k_scan3() {
    int i = blockIdx.x * SCAN_B + threadIdx.x;
    if (i < N_NODES) {
        int incl = g_offs[i + 1] + g_bsum[blockIdx.x];
        g_offs[i + 1] = incl;
        if (i + 1 < N_NODES) g_cursor[i + 1] = incl;
    }
    if (i == 0) { g_offs[0] = 0; g_cursor[0] = 0; }
}

__global__ void k_fill(const int* __restrict__ src, const int* __restrict__ dst) {
    int e = blockIdx.x * blockDim.x + threadIdx.x;
    if (e < N_EDGES) {
        int d = dst[e];
        int pos = atomicAdd(&g_cursor[d], 1);
        g_adj[pos] = src[e];
    }
}

// ---------------- GEMM: C[M,128] = A[M,128] @ W[128,128] ----------------
// 128x128 tile, 256 threads, 8x8 microtile, BK=16.
#define AS_STRIDE 132
__global__ void __launch_bounds__(256) k_gemm(const float* __restrict__ A,
                                              const float* __restrict__ W,
                                              float* __restrict__ C) {
    __shared__ float As[16][AS_STRIDE];   // [k][row]
    __shared__ float Bs[16][128];         // [k][col]
    int tid = threadIdx.x;
    int tx = tid & 15;        // col group
    int ty = tid >> 4;        // row group
    int rowBase = blockIdx.x * 128;

    float acc[8][8];
#pragma unroll
    for (int i = 0; i < 8; i++)
#pragma unroll
        for (int j = 0; j < 8; j++) acc[i][j] = 0.f;

    for (int k0 = 0; k0 < 128; k0 += 16) {
        // A tile: 128 rows x 16 k = 512 float4, 2 per thread, transpose into As[k][row]
#pragma unroll
        for (int i = 0; i < 2; i++) {
            int idx = tid + i * 256;
            int r = idx >> 2;
            int c4 = idx & 3;
            int grow = rowBase + r;
            float4 v = make_float4(0.f, 0.f, 0.f, 0.f);
            if (grow < N_NODES)
                v = *reinterpret_cast<const float4*>(&A[grow * D + k0 + c4 * 4]);
            As[c4 * 4 + 0][r] = v.x;
            As[c4 * 4 + 1][r] = v.y;
            As[c4 * 4 + 2][r] = v.z;
            As[c4 * 4 + 3][r] = v.w;
        }
        // W tile: 16 k x 128 cols = 512 float4, 2 per thread
#pragma unroll
        for (int i = 0; i < 2; i++) {
            int idx = tid + i * 256;
            int r = idx >> 5;
            int c4 = idx & 31;
            *reinterpret_cast<float4*>(&Bs[r][c4 * 4]) =
                *reinterpret_cast<const float4*>(&W[(k0 + r) * D + c4 * 4]);
        }
        __syncthreads();

#pragma unroll
        for (int k = 0; k < 16; k++) {
            float a[8], b[8];
            *reinterpret_cast<float4*>(&a[0]) = *reinterpret_cast<float4*>(&As[k][ty * 8]);
            *reinterpret_cast<float4*>(&a[4]) = *reinterpret_cast<float4*>(&As[k][ty * 8 + 4]);
            *reinterpret_cast<float4*>(&b[0]) = *reinterpret_cast<float4*>(&Bs[k][tx * 8]);
            *reinterpret_cast<float4*>(&b[4]) = *reinterpret_cast<float4*>(&Bs[k][tx * 8 + 4]);
#pragma unroll
            for (int i = 0; i < 8; i++)
#pragma unroll
                for (int j = 0; j < 8; j++) acc[i][j] = fmaf(a[i], b[j], acc[i][j]);
        }
        __syncthreads();
    }

#pragma unroll
    for (int i = 0; i < 8; i++) {
        int row = rowBase + ty * 8 + i;
        if (row < N_NODES) {
            *reinterpret_cast<float4*>(&C[row * D + tx * 8]) =
                make_float4(acc[i][0], acc[i][1], acc[i][2], acc[i][3]);
            *reinterpret_cast<float4*>(&C[row * D + tx * 8 + 4]) =
                make_float4(acc[i][4], acc[i][5], acc[i][6], acc[i][7]);
        }
    }
}

// ---------------- fused gather + self-loop + bias + LN + ReLU ----------------
// One warp per node; 4 features per lane. out[node] = relu(LN(sum + b))
__global__ void __launch_bounds__(256) k_gather(const float* __restrict__ h,
                                                const float* __restrict__ bias,
                                                const float* __restrict__ lng,
                                                const float* __restrict__ lnb,
                                                float* __restrict__ out) {
    int node = blockIdx.x * 8 + (threadIdx.x >> 5);
    if (node >= N_NODES) return;
    int lane = threadIdx.x & 31;
    float di = g_dinv[node];
    int base = node * D + lane * 4;

    // self-loop term
    float4 hv = *reinterpret_cast<const float4*>(&h[base]);
    float sc = di * di;
    float ax = hv.x * sc, ay = hv.y * sc, az = hv.z * sc, aw = hv.w * sc;

    int beg = __ldg(&g_offs[node]);
    int end = __ldg(&g_offs[node + 1]);
    for (int j0 = beg; j0 < end; j0 += 32) {
        int rem = end - j0;
        int n = rem < 32 ? rem : 32;
        int myidx = 0;
        float mydv = 0.f;
        if (lane < n) {
            myidx = __ldg(&g_adj[j0 + lane]);
            mydv = __ldg(&g_dinv[myidx]);
        }
#pragma unroll 4
        for (int jj = 0; jj < n; jj++) {
            int s = __shfl_sync(0xFFFFFFFFu, myidx, jj);
            float nrm = __shfl_sync(0xFFFFFFFFu, mydv, jj) * di;
            float4 v = *reinterpret_cast<const float4*>(&h[s * D + lane * 4]);
            ax = fmaf(v.x, nrm, ax);
            ay = fmaf(v.y, nrm, ay);
            az = fmaf(v.z, nrm, az);
            aw = fmaf(v.w, nrm, aw);
        }
    }

    // + bias
    float4 b4 = *reinterpret_cast<const float4*>(&bias[lane * 4]);
    ax += b4.x; ay += b4.y; az += b4.z; aw += b4.w;

    // LayerNorm
    float s = ax + ay + az + aw;
#pragma unroll
    for (int o = 16; o > 0; o >>= 1) s += __shfl_xor_sync(0xFFFFFFFFu, s, o);
    float mu = s * (1.0f / D);
    float dx = ax - mu, dy = ay - mu, dz = az - mu, dw = aw - mu;
    float sq = dx * dx + dy * dy + dz * dz + dw * dw;
#pragma unroll
    for (int o = 16; o > 0; o >>= 1) sq += __shfl_xor_sync(0xFFFFFFFFu, sq, o);
    float rs = rsqrtf(sq * (1.0f / D) + LN_EPS);

    float4 g4 = *reinterpret_cast<const float4*>(&lng[lane * 4]);
    float4 p4 = *reinterpret_cast<const float4*>(&lnb[lane * 4]);
    float4 o4;
    o4.x = fmaxf(dx * rs * g4.x + p4.x, 0.f);
    o4.y = fmaxf(dy * rs * g4.y + p4.y, 0.f);
    o4.z = fmaxf(dz * rs * g4.z + p4.z, 0.f);
    o4.w = fmaxf(dw * rs * g4.w + p4.w, 0.f);
    *reinterpret_cast<float4*>(&out[base]) = o4;
}

// ---------------- graph mean pool (batch sorted) ----------------
#define POOL_CHUNK 128
__global__ void __launch_bounds__(128) k_pool(const float* __restrict__ h,
                                              const int* __restrict__ batch) {
    int f = threadIdx.x;
    int start = blockIdx.x * POOL_CHUNK;
    if (start >= N_NODES) return;
    int end = min(start + POOL_CHUNK, N_NODES);
    float sum = 0.f;
    int cur = __ldg(&batch[start]);
    for (int n = start; n < end; n++) {
        int gg = __ldg(&batch[n]);
        if (gg != cur) {
            atomicAdd(&g_pooled[cur * D + f], sum);
            sum = 0.f;
            cur = gg;
        }
        sum += h[n * D + f];
    }
    atomicAdd(&g_pooled[cur * D + f], sum);
}

__global__ void __launch_bounds__(256) k_cnt(const int* __restrict__ batch) {
    __shared__ float hist[NGRAPH];
    if (threadIdx.x < NGRAPH) hist[threadIdx.x] = 0.f;
    __syncthreads();
    for (int n = blockIdx.x * blockDim.x + threadIdx.x; n < N_NODES;
         n += gridDim.x * blockDim.x)
        atomicAdd(&hist[batch[n]], 1.0f);
    __syncthreads();
    if (threadIdx.x < NGRAPH) atomicAdd(&g_gcnt[threadIdx.x], hist[threadIdx.x]);
}

// ---------------- head ----------------
__global__ void __launch_bounds__(1024) k_final(const float* __restrict__ lw,
                                                const float* __restrict__ lb,
                                                float* __restrict__ out) {
    int t = threadIdx.x;
    int g = t >> 4;
    int o = t & 15;
    float acc = 0.f;
#pragma unroll 8
    for (int f = 0; f < D; f++) acc += g_pooled[g * D + f] * __ldg(&lw[f * DOUT + o]);
    out[t] = acc / fmaxf(g_gcnt[g], 1.0f) + __ldg(&lb[o]);
}

// ---------------- launch ----------------
extern "C" void kernel_launch(void* const* d_in, const int* in_sizes, int n_in,
                              void* d_out, int out_size) {
    const float* x     = (const float*)d_in[0];
    const int*   ei    = (const int*)d_in[1];
    const int*   src   = ei;
    const int*   dst   = ei + N_EDGES;
    const int*   batch = (const int*)d_in[2];
    const float* W1    = (const float*)d_in[3];
    const float* b1    = (const float*)d_in[4];
    const float* W2    = (const float*)d_in[5];
    const float* b2    = (const float*)d_in[6];
    const float* lng   = (const float*)d_in[7];
    const float* lnb   = (const float*)d_in[8];
    const float* lw    = (const float*)d_in[9];
    const float* lbias = (const float*)d_in[10];
    float* out = (float*)d_out;

    float *pA = nullptr, *pB = nullptr;
    cudaGetSymbolAddress((void**)&pA, g_A);
    cudaGetSymbolAddress((void**)&pB, g_B);

    const int T = 256;
    // CSR build + degrees
    k_init<<<(N_NODES + T - 1) / T, T>>>();
    k_count<<<(N_EDGES + T - 1) / T, T>>>(dst);
    k_dinv<<<(N_NODES + T - 1) / T, T>>>();
    k_scan1<<<SCAN_NB, SCAN_B>>>();
    k_scan2<<<1, 32>>>();
    k_scan3<<<SCAN_NB, SCAN_B>>>();
    k_fill<<<(N_EDGES + T - 1) / T, T>>>(src, dst);

    // layer 1
    k_gemm<<<(N_NODES + 127) / 128, 256>>>(x, W1, pA);
    k_gather<<<(N_NODES + 7) / 8, 256>>>(pA, b1, lng, lnb, pB);
    // layer 2
    k_gemm<<<(N_NODES + 127) / 128, 256>>>(pB, W2, pA);
    k_gather<<<(N_NODES + 7) / 8, 256>>>(pA, b2, lng, lnb, pB);

    // pool + head
    k_pool<<<(N_NODES + POOL_CHUNK - 1) / POOL_CHUNK, 128>>>(pB, batch);
    k_cnt<<<64, 256>>>(batch);
    k_final<<<1, 1024>>>(lw, lbias, out);
}

// round 3
// speedup vs baseline: 2.4281x; 1.3092x over previous
#include <cuda_runtime.h>
#include <cstdint>

#define N_NODES 100000
#define N_EDGES 1600000
#define D 128
#define NGRAPH 64
#define DOUT 16
#define LN_EPS 1e-5f
#define SCAN_B 1024
#define SCAN_NB ((N_NODES + SCAN_B - 1) / SCAN_B)   // 98

// ---------------- scratch (static device globals; no allocation) ----------------
__device__ float g_A[N_NODES * D];
__device__ float g_B[N_NODES * D];
__device__ int   g_cnti[N_NODES];
__device__ int   g_offs[N_NODES + 1];
__device__ int   g_cursor[N_NODES];
__device__ int   g_adj[N_EDGES];
__device__ int   g_bsum[SCAN_NB];
__device__ float g_dinv[N_NODES];
__device__ float g_pooled[NGRAPH * D];
__device__ float g_gcnt[NGRAPH];

// ---------------- init ----------------
__global__ void k_init() {
    int i = blockIdx.x * blockDim.x + threadIdx.x;
    if (i < N_NODES) g_cnti[i] = 0;
    if (i < NGRAPH * D) g_pooled[i] = 0.0f;
    if (i < NGRAPH) g_gcnt[i] = 0.0f;
}

__global__ void k_count(const int* __restrict__ dst) {
    int i = blockIdx.x * blockDim.x + threadIdx.x;
    if (i < N_EDGES) atomicAdd(&g_cnti[dst[i]], 1);
}

__global__ void k_dinv() {
    int i = blockIdx.x * blockDim.x + threadIdx.x;
    if (i < N_NODES) g_dinv[i] = rsqrtf((float)(g_cnti[i] + 1));  // +1 self-loop
}

// ---------------- prefix scan ----------------
__global__ void k_scan1() {
    __shared__ int sh[SCAN_B];
    int i = blockIdx.x * SCAN_B + threadIdx.x;
    int v = (i < N_NODES) ? g_cnti[i] : 0;
    sh[threadIdx.x] = v;
    __syncthreads();
#pragma unroll
    for (int o = 1; o < SCAN_B; o <<= 1) {
        int t = (threadIdx.x >= o) ? sh[threadIdx.x - o] : 0;
        __syncthreads();
        sh[threadIdx.x] += t;
        __syncthreads();
    }
    if (i < N_NODES) g_offs[i + 1] = sh[threadIdx.x];
    if (threadIdx.x == SCAN_B - 1) g_bsum[blockIdx.x] = sh[SCAN_B - 1];
}

__global__ void k_scan2() {
    if (threadIdx.x == 0) {
        int run = 0;
        for (int b = 0; b < SCAN_NB; b++) {
            int t = g_bsum[b];
            g_bsum[b] = run;
            run += t;
        }
    }
}

__global__ void k_scan3() {
    int i = blockIdx.x * SCAN_B + threadIdx.x;
    if (i < N_NODES) {
        int incl = g_offs[i + 1] + g_bsum[blockIdx.x];
        g_offs[i + 1] = incl;
        if (i + 1 < N_NODES) g_cursor[i + 1] = incl;
    }
    if (i == 0) { g_offs[0] = 0; g_cursor[0] = 0; }
}

__global__ void k_fill(const int* __restrict__ src, const int* __restrict__ dst) {
    int e = blockIdx.x * blockDim.x + threadIdx.x;
    if (e < N_EDGES) {
        int d = dst[e];
        int pos = atomicAdd(&g_cursor[d], 1);
        g_adj[pos] = src[e];
    }
}

// ---------------- TF32 tensor-core GEMM: C[M,128] = A[M,128] @ W[128,128] ----------------
// Block: 256 threads (8 warps, 4x2), tile 128x128, k-chunk 32.
// Warp: 32 rows x 64 cols via mma.m16n8k8 (2 m-tiles x 8 n-tiles x 4 k-tiles/chunk).
#define AS_STRIDE 36    // bank pattern (4g + t): conflict-free A-frag loads
#define WS_STRIDE 132   // bank pattern (4t + g): conflict-free B-frag loads

__device__ __forceinline__ uint32_t f2tf32(float f) {
    uint32_t u;
    asm("cvt.rna.tf32.f32 %0, %1;" : "=r"(u) : "f"(f));
    return u;
}

__global__ void __launch_bounds__(256) k_gemm(const float* __restrict__ A,
                                              const float* __restrict__ W,
                                              float* __restrict__ C) {
    __shared__ uint32_t As[128 * AS_STRIDE];   // [row][k0..31]
    __shared__ uint32_t Ws[32 * WS_STRIDE];    // [k][n0..127]
    int tid = threadIdx.x;
    int lane = tid & 31;
    int w = tid >> 5;
    int warpM = (w >> 1) * 32;     // 0,32,64,96
    int warpN = (w & 1) * 64;      // 0,64
    int g = lane >> 2;             // 0..7
    int t = lane & 3;              // 0..3
    int rowBase = blockIdx.x * 128;

    float c[2][8][4];
#pragma unroll
    for (int mi = 0; mi < 2; mi++)
#pragma unroll
        for (int nt = 0; nt < 8; nt++)
#pragma unroll
            for (int q = 0; q < 4; q++) c[mi][nt][q] = 0.f;

    for (int k0 = 0; k0 < 128; k0 += 32) {
        // A chunk: 128 rows x 32 k = 1024 float4, 4 per thread
#pragma unroll
        for (int i = 0; i < 4; i++) {
            int idx = tid + i * 256;
            int r = idx >> 3;
            int c4 = idx & 7;
            int grow = rowBase + r;
            float4 v = make_float4(0.f, 0.f, 0.f, 0.f);
            if (grow < N_NODES)
                v = *reinterpret_cast<const float4*>(&A[grow * D + k0 + c4 * 4]);
            uint32_t* p = &As[r * AS_STRIDE + c4 * 4];
            p[0] = f2tf32(v.x); p[1] = f2tf32(v.y);
            p[2] = f2tf32(v.z); p[3] = f2tf32(v.w);
        }
        // W chunk: 32 k x 128 n = 1024 float4, 4 per thread
#pragma unroll
        for (int i = 0; i < 4; i++) {
            int idx = tid + i * 256;
            int r = idx >> 5;
            int c4 = idx & 31;
            float4 v = *reinterpret_cast<const float4*>(&W[(k0 + r) * D + c4 * 4]);
            uint32_t* p = &Ws[r * WS_STRIDE + c4 * 4];
            p[0] = f2tf32(v.x); p[1] = f2tf32(v.y);
            p[2] = f2tf32(v.z); p[3] = f2tf32(v.w);
        }
        __syncthreads();

#pragma unroll
        for (int kk = 0; kk < 4; kk++) {
            int kb = kk * 8;
            uint32_t af[2][4];
#pragma unroll
            for (int mi = 0; mi < 2; mi++) {
                int r = warpM + mi * 16;
                af[mi][0] = As[(r + g)     * AS_STRIDE + kb + t];
                af[mi][1] = As[(r + g + 8) * AS_STRIDE + kb + t];
                af[mi][2] = As[(r + g)     * AS_STRIDE + kb + t + 4];
                af[mi][3] = As[(r + g + 8) * AS_STRIDE + kb + t + 4];
            }
#pragma unroll
            for (int nt = 0; nt < 8; nt++) {
                int nb = warpN + nt * 8;
                uint32_t b0 = Ws[(kb + t)     * WS_STRIDE + nb + g];
                uint32_t b1 = Ws[(kb + t + 4) * WS_STRIDE + nb + g];
#pragma unroll
                for (int mi = 0; mi < 2; mi++) {
                    asm volatile(
                        "mma.sync.aligned.m16n8k8.row.col.f32.tf32.tf32.f32 "
                        "{%0,%1,%2,%3}, {%4,%5,%6,%7}, {%8,%9}, {%0,%1,%2,%3};"
                        : "+f"(c[mi][nt][0]), "+f"(c[mi][nt][1]),
                          "+f"(c[mi][nt][2]), "+f"(c[mi][nt][3])
                        : "r"(af[mi][0]), "r"(af[mi][1]), "r"(af[mi][2]), "r"(af[mi][3]),
                          "r"(b0), "r"(b1));
                }
            }
        }
        __syncthreads();
    }

    // epilogue: c0,c1 at (g, 2t), c2,c3 at (g+8, 2t)
#pragma unroll
    for (int mi = 0; mi < 2; mi++) {
#pragma unroll
        for (int nt = 0; nt < 8; nt++) {
            int colBase = warpN + nt * 8 + t * 2;
            int r0 = rowBase + warpM + mi * 16 + g;
            int r1 = r0 + 8;
            if (r0 < N_NODES)
                *reinterpret_cast<float2*>(&C[r0 * D + colBase]) =
                    make_float2(c[mi][nt][0], c[mi][nt][1]);
            if (r1 < N_NODES)
                *reinterpret_cast<float2*>(&C[r1 * D + colBase]) =
                    make_float2(c[mi][nt][2], c[mi][nt][3]);
        }
    }
}

// ---------------- fused gather + self-loop + bias + LN + ReLU ----------------
__global__ void __launch_bounds__(256) k_gather(const float* __restrict__ h,
                                                const float* __restrict__ bias,
                                                const float* __restrict__ lng,
                                                const float* __restrict__ lnb,
                                                float* __restrict__ out) {
    int node = blockIdx.x * 8 + (threadIdx.x >> 5);
    if (node >= N_NODES) return;
    int lane = threadIdx.x & 31;
    float di = g_dinv[node];
    int base = node * D + lane * 4;

    float4 hv = *reinterpret_cast<const float4*>(&h[base]);
    float sc = di * di;
    float ax = hv.x * sc, ay = hv.y * sc, az = hv.z * sc, aw = hv.w * sc;

    int beg = __ldg(&g_offs[node]);
    int end = __ldg(&g_offs[node + 1]);
    for (int j0 = beg; j0 < end; j0 += 32) {
        int rem = end - j0;
        int n = rem < 32 ? rem : 32;
        int myidx = 0;
        float mydv = 0.f;
        if (lane < n) {
            myidx = __ldg(&g_adj[j0 + lane]);
            mydv = __ldg(&g_dinv[myidx]);
        }
#pragma unroll 4
        for (int jj = 0; jj < n; jj++) {
            int s = __shfl_sync(0xFFFFFFFFu, myidx, jj);
            float nrm = __shfl_sync(0xFFFFFFFFu, mydv, jj) * di;
            float4 v = *reinterpret_cast<const float4*>(&h[s * D + lane * 4]);
            ax = fmaf(v.x, nrm, ax);
            ay = fmaf(v.y, nrm, ay);
            az = fmaf(v.z, nrm, az);
            aw = fmaf(v.w, nrm, aw);
        }
    }

    float4 b4 = *reinterpret_cast<const float4*>(&bias[lane * 4]);
    ax += b4.x; ay += b4.y; az += b4.z; aw += b4.w;

    float s = ax + ay + az + aw;
#pragma unroll
    for (int o = 16; o > 0; o >>= 1) s += __shfl_xor_sync(0xFFFFFFFFu, s, o);
    float mu = s * (1.0f / D);
    float dx = ax - mu, dy = ay - mu, dz = az - mu, dw = aw - mu;
    float sq = dx * dx + dy * dy + dz * dz + dw * dw;
#pragma unroll
    for (int o = 16; o > 0; o >>= 1) sq += __shfl_xor_sync(0xFFFFFFFFu, sq, o);
    float rs = rsqrtf(sq * (1.0f / D) + LN_EPS);

    float4 g4 = *reinterpret_cast<const float4*>(&lng[lane * 4]);
    float4 p4 = *reinterpret_cast<const float4*>(&lnb[lane * 4]);
    float4 o4;
    o4.x = fmaxf(dx * rs * g4.x + p4.x, 0.f);
    o4.y = fmaxf(dy * rs * g4.y + p4.y, 0.f);
    o4.z = fmaxf(dz * rs * g4.z + p4.z, 0.f);
    o4.w = fmaxf(dw * rs * g4.w + p4.w, 0.f);
    *reinterpret_cast<float4*>(&out[base]) = o4;
}

// ---------------- graph mean pool (batch sorted) ----------------
#define POOL_CHUNK 128
__global__ void __launch_bounds__(128) k_pool(const float* __restrict__ h,
                                              const int* __restrict__ batch) {
    int f = threadIdx.x;
    int start = blockIdx.x * POOL_CHUNK;
    if (start >= N_NODES) return;
    int end = min(start + POOL_CHUNK, N_NODES);
    float sum = 0.f;
    int cur = __ldg(&batch[start]);
    for (int n = start; n < end; n++) {
        int gg = __ldg(&batch[n]);
        if (gg != cur) {
            atomicAdd(&g_pooled[cur * D + f], sum);
            sum = 0.f;
            cur = gg;
        }
        sum += h[n * D + f];
    }
    atomicAdd(&g_pooled[cur * D + f], sum);
}

__global__ void __launch_bounds__(256) k_cnt(const int* __restrict__ batch) {
    __shared__ float hist[NGRAPH];
    if (threadIdx.x < NGRAPH) hist[threadIdx.x] = 0.f;
    __syncthreads();
    for (int n = blockIdx.x * blockDim.x + threadIdx.x; n < N_NODES;
         n += gridDim.x * blockDim.x)
        atomicAdd(&hist[batch[n]], 1.0f);
    __syncthreads();
    if (threadIdx.x < NGRAPH) atomicAdd(&g_gcnt[threadIdx.x], hist[threadIdx.x]);
}

// ---------------- head ----------------
__global__ void __launch_bounds__(1024) k_final(const float* __restrict__ lw,
                                                const float* __restrict__ lb,
                                                float* __restrict__ out) {
    int t = threadIdx.x;
    int g = t >> 4;
    int o = t & 15;
    float acc = 0.f;
#pragma unroll 8
    for (int f = 0; f < D; f++) acc += g_pooled[g * D + f] * __ldg(&lw[f * DOUT + o]);
    out[t] = acc / fmaxf(g_gcnt[g], 1.0f) + __ldg(&lb[o]);
}

// ---------------- launch ----------------
extern "C" void kernel_launch(void* const* d_in, const int* in_sizes, int n_in,
                              void* d_out, int out_size) {
    const float* x     = (const float*)d_in[0];
    const int*   ei    = (const int*)d_in[1];
    const int*   src   = ei;
    const int*   dst   = ei + N_EDGES;
    const int*   batch = (const int*)d_in[2];
    const float* W1    = (const float*)d_in[3];
    const float* b1    = (const float*)d_in[4];
    const float* W2    = (const float*)d_in[5];
    const float* b2    = (const float*)d_in[6];
    const float* lng   = (const float*)d_in[7];
    const float* lnb   = (const float*)d_in[8];
    const float* lw    = (const float*)d_in[9];
    const float* lbias = (const float*)d_in[10];
    float* out = (float*)d_out;

    float *pA = nullptr, *pB = nullptr;
    cudaGetSymbolAddress((void**)&pA, g_A);
    cudaGetSymbolAddress((void**)&pB, g_B);

    const int T = 256;
    // CSR build + degrees
    k_init<<<(N_NODES + T - 1) / T, T>>>();
    k_count<<<(N_EDGES + T - 1) / T, T>>>(dst);
    k_dinv<<<(N_NODES + T - 1) / T, T>>>();
    k_scan1<<<SCAN_NB, SCAN_B>>>();
    k_scan2<<<1, 32>>>();
    k_scan3<<<SCAN_NB, SCAN_B>>>();
    k_fill<<<(N_EDGES + T - 1) / T, T>>>(src, dst);

    // layer 1
    k_gemm<<<(N_NODES + 127) / 128, 256>>>(x, W1, pA);
    k_gather<<<(N_NODES + 7) / 8, 256>>>(pA, b1, lng, lnb, pB);
    // layer 2
    k_gemm<<<(N_NODES + 127) / 128, 256>>>(pB, W2, pA);
    k_gather<<<(N_NODES + 7) / 8, 256>>>(pA, b2, lng, lnb, pB);

    // pool + head
    k_pool<<<(N_NODES + POOL_CHUNK - 1) / POOL_CHUNK, 128>>>(pB, batch);
    k_cnt<<<64, 256>>>(batch);
    k_final<<<1, 1024>>>(lw, lbias, out);
}